// round 15
// baseline (speedup 1.0000x reference)
#include <cuda_runtime.h>
#include <cuda_bf16.h>
#include <cstdint>
#include <cstddef>

// ---------------- problem constants ----------------
#define B_  8
#define S_  1024
#define D_  1024
#define H_  8
#define HD_ 64
#define HID_ 512
#define P_  2048
#define TOK (B_ * S_)
#define EPS 1e-6f
#define CAP 15.0f

#define KE_XN 3072
#define KE_P  6144
#define KE_UB 1536

// ---------------- static device scratch ----------------
__device__ __align__(128) float g_rt  [(size_t)TOK * HID_];
__device__ __align__(128) float g_skip[(size_t)TOK * HID_];
__device__ __align__(128) float g_q   [(size_t)TOK * HID_];
__device__ __align__(128) float g_k   [(size_t)TOK * HID_];
__device__ __align__(128) float g_v   [(size_t)TOK * HID_];
__device__ __align__(128) float g_o   [(size_t)TOK * HID_];
__device__ __align__(128) float g_i   [(size_t)TOK * H_];
__device__ __align__(128) float g_f   [(size_t)TOK * H_];
__device__ __align__(128) float g_hs  [(size_t)TOK * HID_];

__device__ __align__(128) __nv_bfloat16 g_xn2 [(size_t)TOK * 2048];
__device__ __align__(128) __nv_bfloat16 g_xt2 [(size_t)TOK * 4096];
__device__ __align__(128) __nv_bfloat16 g_xc2 [(size_t)TOK * 4096];
__device__ __align__(128) __nv_bfloat16 g_ub2 [(size_t)TOK * 1024];
__device__ __align__(128) __nv_bfloat16 g_wup  [(size_t)2560 * KE_XN];  // up_l|up_r
__device__ __align__(128) __nv_bfloat16 g_wqkif[(size_t)1152 * KE_P];   // q|k|i|f|pad0
__device__ __align__(128) __nv_bfloat16 g_wskip[(size_t)512  * KE_P];
__device__ __align__(128) __nv_bfloat16 g_wv   [(size_t)512  * KE_P];
__device__ __align__(128) __nv_bfloat16 g_wo   [(size_t)512  * KE_P];
__device__ __align__(128) __nv_bfloat16 g_wdn  [(size_t)1024 * KE_UB];

// ---------------- mma.sync GEMM config ----------------
#define MTILE 128
#define NTILE 128
#define BKE   64
#define ROWB  144
#define STAGE_A (MTILE * ROWB)
#define STAGE_B (NTILE * ROWB)
#define STAGE_BYTES (STAGE_A + STAGE_B)
#define GSMEM (3 * STAGE_BYTES)       // 110592; 2 CTAs/SM = 216 KB <= 228 KB carveout

__device__ __forceinline__ uint32_t smem_u32(const void* p) {
    uint32_t a;
    asm("{ .reg .u64 t; cvta.to.shared.u64 t, %1; cvt.u32.u64 %0, t; }" : "=r"(a) : "l"(p));
    return a;
}

__device__ __forceinline__ void ldsm4(uint32_t& r0, uint32_t& r1, uint32_t& r2, uint32_t& r3,
                                      uint32_t addr) {
    asm volatile("ldmatrix.sync.aligned.m8n8.x4.shared.b16 {%0,%1,%2,%3}, [%4];"
                 : "=r"(r0), "=r"(r1), "=r"(r2), "=r"(r3) : "r"(addr));
}

__device__ __forceinline__ void mma_bf16(float& c0, float& c1, float& c2, float& c3,
                                         uint32_t a0, uint32_t a1, uint32_t a2, uint32_t a3,
                                         uint32_t b0, uint32_t b1) {
    asm volatile(
        "mma.sync.aligned.m16n8k16.row.col.f32.bf16.bf16.f32 "
        "{%0,%1,%2,%3}, {%4,%5,%6,%7}, {%8,%9}, {%0,%1,%2,%3};"
        : "+f"(c0), "+f"(c1), "+f"(c2), "+f"(c3)
        : "r"(a0), "r"(a1), "r"(a2), "r"(a3), "r"(b0), "r"(b1));
}

__device__ __forceinline__ void split2(float v, __nv_bfloat16& hi, __nv_bfloat16& lo) {
    hi = __float2bfloat16(v);
    lo = __float2bfloat16(v - __bfloat162float(hi));
}

// ---------------- shared GEMM core: 3-stage pipeline + acc -> smem tile (pitch 130) ----------------
template<int KE>
__device__ __forceinline__ void gemm_core(
    const __nv_bfloat16* __restrict__ A, const __nv_bfloat16* __restrict__ W,
    char* dsm, int m0, int n0)
{
    const uint32_t sbase = smem_u32(dsm);
    const int tid = threadIdx.x;
    const int wid = tid >> 5, lane = tid & 31;
    const int warp_m = wid >> 1;
    const int warp_n = wid & 1;

    constexpr int NS = KE / BKE;
    constexpr int KB = KE / 3 / BKE;
    constexpr int AW = (KE / 3) * 2;

    auto load_stage = [&](int ss, int buf) {
        const int ass = (ss >= 2 * KB) ? ss - 2 * KB : ss;
        const uint32_t sa = sbase + buf * STAGE_BYTES;
        #pragma unroll
        for (int j = 0; j < 4; j++) {
            int cid = tid + j * 256;
            int r = cid >> 3, cg = cid & 7;
            const char* gA = (const char*)A + ((size_t)(m0 + r) * AW + ass * BKE) * 2 + cg * 16;
            asm volatile("cp.async.cg.shared.global [%0], [%1], 16;"
                         :: "r"(sa + r * ROWB + cg * 16), "l"(gA));
            const char* gB = (const char*)W + ((size_t)(n0 + r) * KE + ss * BKE) * 2 + cg * 16;
            asm volatile("cp.async.cg.shared.global [%0], [%1], 16;"
                         :: "r"(sa + STAGE_A + r * ROWB + cg * 16), "l"(gB));
        }
    };

    float acc[2][8][4];
    #pragma unroll
    for (int i = 0; i < 2; i++)
        #pragma unroll
        for (int j = 0; j < 8; j++)
            #pragma unroll
            for (int c = 0; c < 4; c++) acc[i][j][c] = 0.f;

    load_stage(0, 0);
    asm volatile("cp.async.commit_group;");
    load_stage(1, 1);
    asm volatile("cp.async.commit_group;");

    const int a_row = lane & 15;
    const int a_kh  = lane >> 4;
    const int b_row = (lane & 7) | ((lane >> 4) << 3);
    const int b_kh  = (lane >> 3) & 1;

    #pragma unroll 3
    for (int s = 0; s < NS; s++) {
        const int buf = s % 3;
        asm volatile("cp.async.wait_group 1;");
        __syncthreads();          // stage s visible to all; all compute on buf done last round

        if (s + 2 < NS) load_stage(s + 2, (s + 2) % 3);
        asm volatile("cp.async.commit_group;");

        const uint32_t sa = sbase + buf * STAGE_BYTES;
        const uint32_t sb = sa + STAGE_A;

        #pragma unroll
        for (int ks = 0; ks < 4; ks++) {
            uint32_t afr[2][4];
            #pragma unroll
            for (int mt = 0; mt < 2; mt++) {
                uint32_t addr = sa + (warp_m * 32 + mt * 16 + a_row) * ROWB
                              + ks * 32 + a_kh * 16;
                ldsm4(afr[mt][0], afr[mt][1], afr[mt][2], afr[mt][3], addr);
            }
            uint32_t bfr[4][4];
            #pragma unroll
            for (int np = 0; np < 4; np++) {
                uint32_t addr = sb + (warp_n * 64 + np * 16 + b_row) * ROWB
                              + ks * 32 + b_kh * 16;
                ldsm4(bfr[np][0], bfr[np][1], bfr[np][2], bfr[np][3], addr);
            }
            #pragma unroll
            for (int mt = 0; mt < 2; mt++)
                #pragma unroll
                for (int nt = 0; nt < 8; nt++)
                    mma_bf16(acc[mt][nt][0], acc[mt][nt][1], acc[mt][nt][2], acc[mt][nt][3],
                             afr[mt][0], afr[mt][1], afr[mt][2], afr[mt][3],
                             bfr[nt >> 1][(nt & 1) * 2], bfr[nt >> 1][(nt & 1) * 2 + 1]);
        }
    }

    __syncthreads();
    float* tile = (float*)dsm;
    const int er = lane >> 2;
    const int ec = (lane & 3) * 2;
    #pragma unroll
    for (int mt = 0; mt < 2; mt++) {
        #pragma unroll
        for (int nt = 0; nt < 8; nt++) {
            int rl = warp_m * 32 + mt * 16 + er;
            int cl = warp_n * 64 + nt * 8 + ec;
            tile[rl * 130 + cl]           = acc[mt][nt][0];
            tile[rl * 130 + cl + 1]       = acc[mt][nt][1];
            tile[(rl + 8) * 130 + cl]     = acc[mt][nt][2];
            tile[(rl + 8) * 130 + cl + 1] = acc[mt][nt][3];
        }
    }
    __syncthreads();
}

// MODE: 0 UP (n<2048: xt2 dual | n>=2048: rt)   4 DOWN (+bias+resid)
template<int MODE, int KE>
__global__ void __launch_bounds__(256, 2) gemm_mma(
    const __nv_bfloat16* __restrict__ A, const __nv_bfloat16* __restrict__ W,
    const float* __restrict__ b0, const float* __restrict__ b1,
    const float* __restrict__ resid,
    float* __restrict__ o0, float* __restrict__ o1)
{
    extern __shared__ __align__(128) char dsm[];
    const int m0 = blockIdx.y * MTILE;
    const int n0 = blockIdx.x * NTILE;
    gemm_core<KE>(A, W, dsm, m0, n0);

    float* tile = (float*)dsm;
    const int tid = threadIdx.x;
    const int col = tid & 127;
    const int rb  = tid >> 7;
    const int n   = n0 + col;

    if (MODE == 0) {
        if (n < 2048) {
            const float bias = b0[n];
            __nv_bfloat16* xt2 = (__nv_bfloat16*)o0;
            for (int rr = rb; rr < 128; rr += 2) {
                float v = tile[rr * 130 + col] + bias;
                __nv_bfloat16 hi, lo; split2(v, hi, lo);
                size_t base = (size_t)(m0 + rr) * 4096 + n;
                xt2[base] = hi; xt2[base + 2048] = lo;
            }
        } else {
            const int nn = n - 2048;
            const float bias = b1[nn];
            for (int rr = rb; rr < 128; rr += 2)
                o1[(size_t)(m0 + rr) * 512 + nn] = tile[rr * 130 + col] + bias;
        }
    } else {
        const float bias = b0[n];
        for (int rr = rb; rr < 128; rr += 2) {
            size_t gi = (size_t)(m0 + rr) * 1024 + n;
            o0[gi] = tile[rr * 130 + col] + bias + resid[gi];
        }
    }
}

// ---------------- merged qkif (from xc) + v (from xt) GEMM launch ----------------
// grid 832: bid<576 -> qkif tile; else v tile.
__global__ void __launch_bounds__(256, 2) qkif_v(
    const __nv_bfloat16* __restrict__ xc2, const __nv_bfloat16* __restrict__ xt2,
    const __nv_bfloat16* __restrict__ wqkif, const __nv_bfloat16* __restrict__ wv,
    const float* __restrict__ bq, const float* __restrict__ bk,
    const float* __restrict__ bi, const float* __restrict__ bf,
    const float* __restrict__ bv,
    float* __restrict__ q, float* __restrict__ k,
    float* __restrict__ ib, float* __restrict__ fb, float* __restrict__ vb)
{
    extern __shared__ __align__(128) char dsm[];
    const int bid = blockIdx.x;
    const int tid = threadIdx.x;
    const bool isv = bid >= 576;

    int m0, n0;
    if (!isv) { m0 = (bid / 9) * MTILE; n0 = (bid % 9) * NTILE; }
    else      { int idx = bid - 576; m0 = (idx >> 2) * MTILE; n0 = (idx & 3) * NTILE; }

    gemm_core<KE_P>(isv ? xt2 : xc2, isv ? wv : wqkif, dsm, m0, n0);

    float* tile = (float*)dsm;
    const int col = tid & 127;
    const int rb  = tid >> 7;
    const int n   = n0 + col;

    if (isv) {
        const float bias = bv[n];
        for (int rr = rb; rr < 128; rr += 2)
            vb[(size_t)(m0 + rr) * 512 + n] = tile[rr * 130 + col] + bias;
    } else if (n < 512) {
        const float bias = bq[n];
        for (int rr = rb; rr < 128; rr += 2)
            q[(size_t)(m0 + rr) * 512 + n] = tile[rr * 130 + col] + bias;
    } else if (n < 1024) {
        const int nn = n - 512;
        const float bias = bk[nn];
        for (int rr = rb; rr < 128; rr += 2)
            k[(size_t)(m0 + rr) * 512 + nn] = (tile[rr * 130 + col] + bias) * 0.125f;
    } else {
        const int gi = n - 1024;
        if (gi < 16) {
            float* op = gi < 8 ? ib : fb;
            const float bias = gi < 8 ? bi[gi] : bf[gi - 8];
            const int hh = gi & 7;
            for (int rr = rb; rr < 128; rr += 2) {
                float v = tile[rr * 130 + col] + bias;
                op[(size_t)(m0 + rr) * H_ + hh] = CAP * tanhf(v * (1.0f / CAP));
            }
        }
    }
}

// ---------------- fused: skip GEMM + o GEMM + sequential recurrence ----------------
// grid 576: bid<64 -> recurrence; else GEMM tile (256 skip + 256 o).
__global__ void __launch_bounds__(256, 2) skip_o_recur(
    const __nv_bfloat16* __restrict__ xc2, const __nv_bfloat16* __restrict__ xt2,
    const __nv_bfloat16* __restrict__ wskip, const __nv_bfloat16* __restrict__ wo,
    const float* __restrict__ bskip, const float* __restrict__ bo,
    float* __restrict__ skip, float* __restrict__ ob,
    const float* __restrict__ q, const float* __restrict__ k, const float* __restrict__ v,
    const float* __restrict__ ip, const float* __restrict__ fp, float* __restrict__ hs)
{
    extern __shared__ __align__(128) char dsm[];
    const int bid = blockIdx.x;
    const int tid = threadIdx.x;

    if (bid >= 64) {
        const int idx = bid - 64;
        const bool iso = idx >= 256;
        const int t2 = idx & 255;
        const int m0 = (t2 >> 2) * MTILE;
        const int n0 = (t2 & 3) * NTILE;
        const __nv_bfloat16* A = iso ? xt2 : xc2;
        const __nv_bfloat16* W = iso ? wo : wskip;
        gemm_core<KE_P>(A, W, dsm, m0, n0);

        float* tile = (float*)dsm;
        const int col = tid & 127;
        const int rb  = tid >> 7;
        const int n   = n0 + col;
        const float bias = iso ? bo[n] : bskip[n];
        float* op = iso ? ob : skip;
        for (int rr = rb; rr < 128; rr += 2) {
            float x = tile[rr * 130 + col] + bias;
            if (iso) x = 1.0f / (1.0f + __expf(-x));
            op[(size_t)(m0 + rr) * 512 + n] = x;
        }
        return;
    }

    // ---- recurrence part: 64 blocks x 256 threads ----
    int bh = bid;
    int b = bh >> 3, h = bh & 7;
    int t = tid;
    int d = t & 63, quarter = t >> 6;

    __shared__ __align__(16) float q_s[64], k_s[64], v_s[64];
    __shared__ float n_s[64];
    __shared__ float num_s[256];
    __shared__ float den_s[2];

    float c[16];
    #pragma unroll
    for (int j = 0; j < 16; j++) c[j] = 0.f;
    if (t < 64) n_s[t] = 1.f;
    float m = 0.f;

    size_t gbase = (size_t)b * S_ * HID_ + (size_t)h * HD_ + d;
    size_t ifbase = (size_t)b * S_ * H_ + h;

    float qr = 0.f, kr = 0.f, vr = 0.f;
    if (t < 64) { qr = q[gbase]; kr = k[gbase]; vr = v[gbase]; }
    float ir = ip[ifbase], fr = fp[ifbase];

    for (int s = 0; s < S_; s++) {
        if (t < 64) { q_s[t] = qr; k_s[t] = kr; v_s[t] = vr; }
        float it = ir, ft = fr;
        __syncthreads();

        if (s + 1 < S_) {
            size_t off = gbase + (size_t)(s + 1) * HID_;
            if (t < 64) { qr = q[off]; kr = k[off]; vr = v[off]; }
            size_t ioff = ifbase + (size_t)(s + 1) * H_;
            ir = ip[ioff]; fr = fp[ioff];
        }

        float m_t = fmaxf(ft + m, it);
        float ie  = __expf(it - m_t);
        float fe  = __expf(ft - m_t + m);
        m = m_t;

        float ievd = ie * v_s[d];
        float np0 = 0.f, np1 = 0.f, np2 = 0.f, np3 = 0.f;
        const float4* k4 = (const float4*)(k_s + quarter * 16);
        const float4* q4 = (const float4*)(q_s + quarter * 16);
        #pragma unroll
        for (int j = 0; j < 4; j++) {
            float4 kk = k4[j], qq = q4[j];
            float c0 = fmaf(fe, c[4 * j + 0], ievd * kk.x); c[4 * j + 0] = c0; np0 = fmaf(c0, qq.x, np0);
            float c1 = fmaf(fe, c[4 * j + 1], ievd * kk.y); c[4 * j + 1] = c1; np1 = fmaf(c1, qq.y, np1);
            float c2 = fmaf(fe, c[4 * j + 2], ievd * kk.z); c[4 * j + 2] = c2; np2 = fmaf(c2, qq.z, np2);
            float c3 = fmaf(fe, c[4 * j + 3], ievd * kk.w); c[4 * j + 3] = c3; np3 = fmaf(c3, qq.w, np3);
        }
        num_s[t] = (np0 + np1) + (np2 + np3);

        float denp = 0.f;
        if (t < 64) {
            float nn = fmaf(fe, n_s[t], ie * k_s[t]);
            n_s[t] = nn;
            denp = nn * q_s[t];
        }
        #pragma unroll
        for (int o = 16; o > 0; o >>= 1) denp += __shfl_down_sync(0xffffffffu, denp, o);
        if (t < 64 && (t & 31) == 0) den_s[t >> 5] = denp;
        __syncthreads();

        if (t < 64) {
            float den = fmaxf(den_s[0] + den_s[1], 1.0f);
            hs[gbase + (size_t)s * HID_] =
                ((num_s[t] + num_s[64 + t]) + (num_s[128 + t] + num_s[192 + t])) / den;
        }
    }
}

// ---------------- prep: weight convert (blocks 0..32895) + layernorm (32896..41087) ----------------
__global__ void prep_kernel(
    const float* __restrict__ Wupl, const float* __restrict__ Wupr,
    const float* __restrict__ Wq, const float* __restrict__ Wk,
    const float* __restrict__ Wi, const float* __restrict__ Wf,
    const float* __restrict__ Wskip, const float* __restrict__ Wv,
    const float* __restrict__ Wo, const float* __restrict__ Wdn,
    const float* __restrict__ x, const float* __restrict__ lng, const float* __restrict__ lnb,
    __nv_bfloat16* __restrict__ wup, __nv_bfloat16* __restrict__ wqkif,
    __nv_bfloat16* __restrict__ wskip, __nv_bfloat16* __restrict__ wv,
    __nv_bfloat16* __restrict__ wo, __nv_bfloat16* __restrict__ wdn,
    __nv_bfloat16* __restrict__ xn2)
{
    __shared__ float ps1[8], ps2[8];
    const int bid = blockIdx.x;
    const int tid = threadIdx.x;

    if (bid >= 32896) {
        // ---- layernorm: one token per block ----
        int tok = bid - 32896;
        const float4* xr = (const float4*)(x + (size_t)tok * D_);
        float4 v = xr[tid];
        float s1 = v.x + v.y + v.z + v.w;
        float s2 = v.x * v.x + v.y * v.y + v.z * v.z + v.w * v.w;
        for (int o = 16; o > 0; o >>= 1) {
            s1 += __shfl_down_sync(0xffffffffu, s1, o);
            s2 += __shfl_down_sync(0xffffffffu, s2, o);
        }
        int wid = tid >> 5, lane = tid & 31;
        if (lane == 0) { ps1[wid] = s1; ps2[wid] = s2; }
        __syncthreads();
        float S1 = 0.f, S2 = 0.f;
        #pragma unroll
        for (int w = 0; w < 8; w++) { S1 += ps1[w]; S2 += ps2[w]; }
        float mu = S1 * (1.0f / D_);
        float var = S2 * (1.0f / D_) - mu * mu;
        float r = rsqrtf(var + EPS);

        float4 gv = ((const float4*)lng)[tid];
        float4 bv = ((const float4*)lnb)[tid];
        float vals[4] = { (v.x - mu) * r * gv.x + bv.x, (v.y - mu) * r * gv.y + bv.y,
                          (v.z - mu) * r * gv.z + bv.z, (v.w - mu) * r * gv.w + bv.w };
        __nv_bfloat16 h[4], l[4];
        #pragma unroll
        for (int i = 0; i < 4; i++) split2(vals[i], h[i], l[i]);
        size_t base = (size_t)tok * 2048 + tid * 4;
        *(__nv_bfloat162*)(xn2 + base)            = __nv_bfloat162(h[0], h[1]);
        *(__nv_bfloat162*)(xn2 + base + 2)        = __nv_bfloat162(h[2], h[3]);
        *(__nv_bfloat162*)(xn2 + base + 1024)     = __nv_bfloat162(l[0], l[1]);
        *(__nv_bfloat162*)(xn2 + base + 1024 + 2) = __nv_bfloat162(l[2], l[3]);
        return;
    }

    int idx = bid * 256 + tid;
    const float* src; __nv_bfloat16* dst; int K, KE, rowOff, local;
    if      (idx < 2097152) { src = Wupl;  dst = wup;   K = 1024; KE = KE_XN; rowOff = 0;    local = idx; }
    else if (idx < 2621440) { src = Wupr;  dst = wup;   K = 1024; KE = KE_XN; rowOff = 2048; local = idx - 2097152; }
    else if (idx < 3670016) { src = Wq;    dst = wqkif; K = 2048; KE = KE_P;  rowOff = 0;    local = idx - 2621440; }
    else if (idx < 4718592) { src = Wk;    dst = wqkif; K = 2048; KE = KE_P;  rowOff = 512;  local = idx - 3670016; }
    else if (idx < 4734976) { src = Wi;    dst = wqkif; K = 2048; KE = KE_P;  rowOff = 1024; local = idx - 4718592; }
    else if (idx < 4751360) { src = Wf;    dst = wqkif; K = 2048; KE = KE_P;  rowOff = 1032; local = idx - 4734976; }
    else if (idx < 5799936) { src = Wskip; dst = wskip; K = 2048; KE = KE_P;  rowOff = 0;    local = idx - 4751360; }
    else if (idx < 6848512) { src = Wv;    dst = wv;    K = 2048; KE = KE_P;  rowOff = 0;    local = idx - 5799936; }
    else if (idx < 7897088) { src = Wo;    dst = wo;    K = 2048; KE = KE_P;  rowOff = 0;    local = idx - 6848512; }
    else if (idx < 8421376) { src = Wdn;   dst = wdn;   K = 512;  KE = KE_UB; rowOff = 0;    local = idx - 7897088; }
    else return;
    int r = local / K, k = local - r * K;
    __nv_bfloat16 hi, lo;
    split2(src[local], hi, lo);
    size_t b = (size_t)(rowOff + r) * KE + k;
    dst[b] = hi; dst[b + K] = hi; dst[b + 2 * K] = lo;
}

// ---------------- causal feature conv + SiLU: xt2 -> xc2 ----------------
__global__ void conv_silu_kernel(const __nv_bfloat16* __restrict__ xt2,
                                 const float* __restrict__ w, const float* __restrict__ cb,
                                 __nv_bfloat16* __restrict__ xc2)
{
    __shared__ float row[P_];
    int tok = blockIdx.x;
    int tid = threadIdx.x;        // 256
    const __nv_bfloat162* hi2 = (const __nv_bfloat162*)(xt2 + (size_t)tok * 4096);
    const __nv_bfloat162* lo2 = (const __nv_bfloat162*)(xt2 + (size_t)tok * 4096 + 2048);
    #pragma unroll
    for (int i = 0; i < 4; i++) {
        int idx = tid + i * 256;
        __nv_bfloat162 hp = hi2[idx], lp = lo2[idx];
        row[2 * idx]     = __bfloat162float(hp.x) + __bfloat162float(lp.x);
        row[2 * idx + 1] = __bfloat162float(hp.y) + __bfloat162float(lp.y);
    }
    __syncthreads();

    float w0 = w[0], w1 = w[1], w2 = w[2], w3 = w[3];
    float bb = cb[0];
    __nv_bfloat16 h[8], l[8];
    #pragma unroll
    for (int i = 0; i < 8; i++) {
        int p = tid * 8 + i;
        float x3 = row[p];
        float x2 = (p >= 1) ? row[p - 1] : 0.f;
        float x1 = (p >= 2) ? row[p - 2] : 0.f;
        float x0 = (p >= 3) ? row[p - 3] : 0.f;
        float v = bb + w0 * x0 + w1 * x1 + w2 * x2 + w3 * x3;
        v = v / (1.0f + __expf(-v));
        split2(v, h[i], l[i]);
    }
    size_t base = (size_t)tok * 4096 + tid * 8;
    #pragma unroll
    for (int i = 0; i < 4; i++) {
        *(__nv_bfloat162*)(xc2 + base + 2 * i)        = __nv_bfloat162(h[2 * i], h[2 * i + 1]);
        *(__nv_bfloat162*)(xc2 + base + 2048 + 2 * i) = __nv_bfloat162(l[2 * i], l[2 * i + 1]);
    }
}

// ---------------- mix: o*hs, per-head LN, + skip, * silu(r_t) -> ub dual ----------------
__global__ void mix_kernel(const float* __restrict__ hs, const float* __restrict__ o,
                           const float* __restrict__ skip, const float* __restrict__ rt,
                           const float* __restrict__ mhg, const float* __restrict__ mhb,
                           __nv_bfloat16* __restrict__ ub2)
{
    int tok = blockIdx.x;
    int tid = threadIdx.x;          // 512
    int head = tid >> 6;
    size_t idx = (size_t)tok * HID_ + tid;

    float val = o[idx] * hs[idx];
    float s1 = val, s2 = val * val;
    for (int off = 16; off > 0; off >>= 1) {
        s1 += __shfl_down_sync(0xffffffffu, s1, off);
        s2 += __shfl_down_sync(0xffffffffu, s2, off);
    }
    __shared__ float ps1[16], ps2[16];
    int wid = tid >> 5, lane = tid & 31;
    if (lane == 0) { ps1[wid] = s1; ps2[wid] = s2; }
    __syncthreads();
    float S1 = ps1[head * 2] + ps1[head * 2 + 1];
    float S2 = ps2[head * 2] + ps2[head * 2 + 1];
    float mu = S1 * (1.0f / HD_);
    float var = S2 * (1.0f / HD_) - mu * mu;
    float r = rsqrtf(var + EPS);

    float hn = (val - mu) * r * mhg[tid] + mhb[tid];
    float rv = rt[idx];
    float u = (hn + skip[idx]) * (rv / (1.0f + __expf(-rv)));

    __nv_bfloat16 hi, lo;
    split2(u, hi, lo);
    size_t b = (size_t)tok * 1024 + tid;
    ub2[b] = hi; ub2[b + 512] = lo;
}

// ---------------- host launcher ----------------
extern "C" void kernel_launch(void* const* d_in, const int* in_sizes, int n_in,
                              void* d_out, int out_size)
{
    const float* x      = (const float*)d_in[0];
    const float* ln_g   = (const float*)d_in[1];
    const float* ln_b   = (const float*)d_in[2];
    const float* mh_g   = (const float*)d_in[3];
    const float* mh_b   = (const float*)d_in[4];
    const float* W_up_l = (const float*)d_in[5];
    const float* b_up_l = (const float*)d_in[6];
    const float* W_up_r = (const float*)d_in[7];
    const float* b_up_r = (const float*)d_in[8];
    const float* W_down = (const float*)d_in[9];
    const float* b_down = (const float*)d_in[10];
    const float* conv_w = (const float*)d_in[11];
    const float* conv_b = (const float*)d_in[12];
    const float* W_skip = (const float*)d_in[13];
    const float* b_skip = (const float*)d_in[14];
    const float* W_i    = (const float*)d_in[15];
    const float* b_i    = (const float*)d_in[16];
    const float* W_f    = (const float*)d_in[17];
    const float* b_f    = (const float*)d_in[18];
    const float* W_o    = (const float*)d_in[19];
    const float* b_o    = (const float*)d_in[20];
    const float* W_q    = (const float*)d_in[21];
    const float* b_q    = (const float*)d_in[22];
    const float* W_k    = (const float*)d_in[23];
    const float* b_k    = (const float*)d_in[24];
    const float* W_v    = (const float*)d_in[25];
    const float* b_v    = (const float*)d_in[26];
    float* out = (float*)d_out;

    float *rt, *skip, *qb, *kb, *vb, *ob, *ib, *fb, *hsb;
    __nv_bfloat16 *xn2, *xt2, *xc2, *ub2, *wup, *wqkif, *wskip, *wv, *wo, *wdn;
    cudaGetSymbolAddress((void**)&rt,    g_rt);
    cudaGetSymbolAddress((void**)&skip,  g_skip);
    cudaGetSymbolAddress((void**)&qb,    g_q);
    cudaGetSymbolAddress((void**)&kb,    g_k);
    cudaGetSymbolAddress((void**)&vb,    g_v);
    cudaGetSymbolAddress((void**)&ob,    g_o);
    cudaGetSymbolAddress((void**)&ib,    g_i);
    cudaGetSymbolAddress((void**)&fb,    g_f);
    cudaGetSymbolAddress((void**)&hsb,   g_hs);
    cudaGetSymbolAddress((void**)&xn2,   g_xn2);
    cudaGetSymbolAddress((void**)&xt2,   g_xt2);
    cudaGetSymbolAddress((void**)&xc2,   g_xc2);
    cudaGetSymbolAddress((void**)&ub2,   g_ub2);
    cudaGetSymbolAddress((void**)&wup,   g_wup);
    cudaGetSymbolAddress((void**)&wqkif, g_wqkif);
    cudaGetSymbolAddress((void**)&wskip, g_wskip);
    cudaGetSymbolAddress((void**)&wv,    g_wv);
    cudaGetSymbolAddress((void**)&wo,    g_wo);
    cudaGetSymbolAddress((void**)&wdn,   g_wdn);

    cudaFuncSetAttribute((const void*)gemm_mma<0, KE_XN>, cudaFuncAttributeMaxDynamicSharedMemorySize, GSMEM);
    cudaFuncSetAttribute((const void*)gemm_mma<4, KE_UB>, cudaFuncAttributeMaxDynamicSharedMemorySize, GSMEM);
    cudaFuncSetAttribute((const void*)qkif_v,             cudaFuncAttributeMaxDynamicSharedMemorySize, GSMEM);
    cudaFuncSetAttribute((const void*)skip_o_recur,       cudaFuncAttributeMaxDynamicSharedMemorySize, GSMEM);

    // [0] merged weight conversion + layernorm (wqkif rows 1040..1151 stay zero)
    prep_kernel<<<41088, 256>>>(W_up_l, W_up_r, W_q, W_k, W_i, W_f, W_skip, W_v, W_o, W_down,
                                x, ln_g, ln_b,
                                wup, wqkif, wskip, wv, wo, wdn, xn2);

    // [1] merged up projection: xt2 | rt
    {
        dim3 grid(2560 / NTILE, TOK / MTILE);
        gemm_mma<0, KE_XN><<<grid, 256, GSMEM>>>(xn2, wup, b_up_l, b_up_r,
                                                 nullptr, (float*)xt2, rt);
    }

    // [2] causal conv + silu
    conv_silu_kernel<<<TOK, 256>>>(xt2, conv_w, conv_b, xc2);

    // [3] merged q|k|i|f (xc) + v (xt) — one launch, one tail
    qkif_v<<<832, 256, GSMEM>>>(xc2, xt2, wqkif, wv, b_q, b_k, b_i, b_f, b_v,
                                qb, kb, ib, fb, vb);

    // [4] fused: recurrence (64 blocks first) + skip GEMM + o GEMM
    skip_o_recur<<<576, 256, GSMEM>>>(xc2, xt2, wskip, wo, b_skip, b_o, skip, ob,
                                      qb, kb, vb, ib, fb, hsb);

    // [5] mix -> ub dual
    mix_kernel<<<TOK, 512>>>(hsb, ob, skip, rt, mh_g, mh_b, ub2);

    // [6] down projection + bias + residual
    {
        dim3 grid(1024 / NTILE, TOK / MTILE);
        gemm_mma<4, KE_UB><<<grid, 256, GSMEM>>>(ub2, wdn, b_down, nullptr,
                                                 x, out, nullptr);
    }
}

// round 16
// speedup vs baseline: 1.2196x; 1.2196x over previous
#include <cuda_runtime.h>
#include <cuda_fp16.h>
#include <cstdint>
#include <cstddef>

// ---------------- problem constants ----------------
#define B_  8
#define S_  1024
#define D_  1024
#define H_  8
#define HD_ 64
#define HID_ 512
#define P_  2048
#define TOK (B_ * S_)
#define EPS 1e-6f
#define CAP 15.0f

// fp16 2-term K widths (A=[hi|lo], W=[hi|hi])
#define KE_XN 2048
#define KE_P  4096
#define KE_UB 1024

// ---------------- static device scratch ----------------
__device__ __align__(128) float g_rt  [(size_t)TOK * HID_];
__device__ __align__(128) float g_skip[(size_t)TOK * HID_];
__device__ __align__(128) float g_q   [(size_t)TOK * HID_];
__device__ __align__(128) float g_k   [(size_t)TOK * HID_];
__device__ __align__(128) float g_v   [(size_t)TOK * HID_];
__device__ __align__(128) float g_o   [(size_t)TOK * HID_];
__device__ __align__(128) float g_i   [(size_t)TOK * H_];
__device__ __align__(128) float g_f   [(size_t)TOK * H_];
__device__ __align__(128) float g_hs  [(size_t)TOK * HID_];

__device__ __align__(128) __half g_xn2 [(size_t)TOK * KE_XN];
__device__ __align__(128) __half g_xt2 [(size_t)TOK * KE_P];
__device__ __align__(128) __half g_xc2 [(size_t)TOK * KE_P];
__device__ __align__(128) __half g_ub2 [(size_t)TOK * KE_UB];
__device__ __align__(128) __half g_wup  [(size_t)2560 * KE_XN];  // up_l|up_r
__device__ __align__(128) __half g_wqkif[(size_t)1152 * KE_P];   // q|k|i|f|pad0
__device__ __align__(128) __half g_wskip[(size_t)512  * KE_P];
__device__ __align__(128) __half g_wv   [(size_t)512  * KE_P];
__device__ __align__(128) __half g_wo   [(size_t)512  * KE_P];
__device__ __align__(128) __half g_wdn  [(size_t)1024 * KE_UB];

// ---------------- mma.sync GEMM config ----------------
#define MTILE 128
#define NTILE 128
#define BKE   64
#define ROWB  144
#define STAGE_A (MTILE * ROWB)
#define STAGE_B (NTILE * ROWB)
#define STAGE_BYTES (STAGE_A + STAGE_B)
#define GSMEM (2 * STAGE_BYTES)       // 73728; also holds 128x130 fp32 epilogue tile

__device__ __forceinline__ uint32_t smem_u32(const void* p) {
    uint32_t a;
    asm("{ .reg .u64 t; cvta.to.shared.u64 t, %1; cvt.u32.u64 %0, t; }" : "=r"(a) : "l"(p));
    return a;
}

__device__ __forceinline__ void ldsm4(uint32_t& r0, uint32_t& r1, uint32_t& r2, uint32_t& r3,
                                      uint32_t addr) {
    asm volatile("ldmatrix.sync.aligned.m8n8.x4.shared.b16 {%0,%1,%2,%3}, [%4];"
                 : "=r"(r0), "=r"(r1), "=r"(r2), "=r"(r3) : "r"(addr));
}

__device__ __forceinline__ void mma_f16(float& c0, float& c1, float& c2, float& c3,
                                        uint32_t a0, uint32_t a1, uint32_t a2, uint32_t a3,
                                        uint32_t b0, uint32_t b1) {
    asm volatile(
        "mma.sync.aligned.m16n8k16.row.col.f32.f16.f16.f32 "
        "{%0,%1,%2,%3}, {%4,%5,%6,%7}, {%8,%9}, {%0,%1,%2,%3};"
        : "+f"(c0), "+f"(c1), "+f"(c2), "+f"(c3)
        : "r"(a0), "r"(a1), "r"(a2), "r"(a3), "r"(b0), "r"(b1));
}

__device__ __forceinline__ void split2h(float v, __half& hi, __half& lo) {
    hi = __float2half_rn(v);
    lo = __float2half_rn(v - __half2float(hi));
}

// ---------------- shared GEMM core: mainloop + acc -> smem tile (pitch 130) ----------------
template<int KE>
__device__ __forceinline__ void gemm_core(
    const __half* __restrict__ A, const __half* __restrict__ W,
    char* dsm, int m0, int n0)
{
    const uint32_t sbase = smem_u32(dsm);
    const int tid = threadIdx.x;
    const int wid = tid >> 5, lane = tid & 31;
    const int warp_m = wid >> 1;
    const int warp_n = wid & 1;

    constexpr int NS = KE / BKE;

    auto load_stage = [&](int ss, int buf) {
        const uint32_t sa = sbase + buf * STAGE_BYTES;
        #pragma unroll
        for (int j = 0; j < 4; j++) {
            int cid = tid + j * 256;
            int r = cid >> 3, cg = cid & 7;
            const char* gA = (const char*)A + ((size_t)(m0 + r) * KE + ss * BKE) * 2 + cg * 16;
            asm volatile("cp.async.cg.shared.global [%0], [%1], 16;"
                         :: "r"(sa + r * ROWB + cg * 16), "l"(gA));
            const char* gB = (const char*)W + ((size_t)(n0 + r) * KE + ss * BKE) * 2 + cg * 16;
            asm volatile("cp.async.cg.shared.global [%0], [%1], 16;"
                         :: "r"(sa + STAGE_A + r * ROWB + cg * 16), "l"(gB));
        }
    };

    float acc[2][8][4];
    #pragma unroll
    for (int i = 0; i < 2; i++)
        #pragma unroll
        for (int j = 0; j < 8; j++)
            #pragma unroll
            for (int c = 0; c < 4; c++) acc[i][j][c] = 0.f;

    load_stage(0, 0);
    asm volatile("cp.async.commit_group;");

    const int a_row = lane & 15;
    const int a_kh  = lane >> 4;
    const int b_row = (lane & 7) | ((lane >> 4) << 3);
    const int b_kh  = (lane >> 3) & 1;

    #pragma unroll 2
    for (int s = 0; s < NS; s++) {
        const int buf = s & 1;
        asm volatile("cp.async.wait_group 0;");
        __syncthreads();

        if (s + 1 < NS) load_stage(s + 1, (s + 1) & 1);
        asm volatile("cp.async.commit_group;");

        const uint32_t sa = sbase + buf * STAGE_BYTES;
        const uint32_t sb = sa + STAGE_A;

        #pragma unroll
        for (int ks = 0; ks < 4; ks++) {
            uint32_t afr[2][4];
            #pragma unroll
            for (int mt = 0; mt < 2; mt++) {
                uint32_t addr = sa + (warp_m * 32 + mt * 16 + a_row) * ROWB
                              + ks * 32 + a_kh * 16;
                ldsm4(afr[mt][0], afr[mt][1], afr[mt][2], afr[mt][3], addr);
            }
            uint32_t bfr[4][4];
            #pragma unroll
            for (int np = 0; np < 4; np++) {
                uint32_t addr = sb + (warp_n * 64 + np * 16 + b_row) * ROWB
                              + ks * 32 + b_kh * 16;
                ldsm4(bfr[np][0], bfr[np][1], bfr[np][2], bfr[np][3], addr);
            }
            #pragma unroll
            for (int mt = 0; mt < 2; mt++)
                #pragma unroll
                for (int nt = 0; nt < 8; nt++)
                    mma_f16(acc[mt][nt][0], acc[mt][nt][1], acc[mt][nt][2], acc[mt][nt][3],
                            afr[mt][0], afr[mt][1], afr[mt][2], afr[mt][3],
                            bfr[nt >> 1][(nt & 1) * 2], bfr[nt >> 1][(nt & 1) * 2 + 1]);
        }
    }

    __syncthreads();
    float* tile = (float*)dsm;
    const int er = lane >> 2;
    const int ec = (lane & 3) * 2;
    #pragma unroll
    for (int mt = 0; mt < 2; mt++) {
        #pragma unroll
        for (int nt = 0; nt < 8; nt++) {
            int rl = warp_m * 32 + mt * 16 + er;
            int cl = warp_n * 64 + nt * 8 + ec;
            tile[rl * 130 + cl]           = acc[mt][nt][0];
            tile[rl * 130 + cl + 1]       = acc[mt][nt][1];
            tile[(rl + 8) * 130 + cl]     = acc[mt][nt][2];
            tile[(rl + 8) * 130 + cl + 1] = acc[mt][nt][3];
        }
    }
    __syncthreads();
}

// MODE: 0 UP (n<2048: xt2 dual | n>=2048: rt)   4 DOWN (+bias+resid)
template<int MODE, int KE>
__global__ void __launch_bounds__(256, 2) gemm_mma(
    const __half* __restrict__ A, const __half* __restrict__ W,
    const float* __restrict__ b0, const float* __restrict__ b1,
    const float* __restrict__ resid,
    float* __restrict__ o0, float* __restrict__ o1)
{
    extern __shared__ __align__(128) char dsm[];
    const int m0 = blockIdx.y * MTILE;
    const int n0 = blockIdx.x * NTILE;
    gemm_core<KE>(A, W, dsm, m0, n0);

    float* tile = (float*)dsm;
    const int tid = threadIdx.x;
    const int col = tid & 127;
    const int rb  = tid >> 7;
    const int n   = n0 + col;

    if (MODE == 0) {
        if (n < 2048) {
            const float bias = b0[n];
            __half* xt2 = (__half*)o0;
            for (int rr = rb; rr < 128; rr += 2) {
                float v = tile[rr * 130 + col] + bias;
                __half hi, lo; split2h(v, hi, lo);
                size_t base = (size_t)(m0 + rr) * 4096 + n;
                xt2[base] = hi; xt2[base + 2048] = lo;
            }
        } else {
            const int nn = n - 2048;
            const float bias = b1[nn];
            for (int rr = rb; rr < 128; rr += 2)
                o1[(size_t)(m0 + rr) * 512 + nn] = tile[rr * 130 + col] + bias;
        }
    } else {
        const float bias = b0[n];
        for (int rr = rb; rr < 128; rr += 2) {
            size_t gi = (size_t)(m0 + rr) * 1024 + n;
            o0[gi] = tile[rr * 130 + col] + bias + resid[gi];
        }
    }
}

// ---------------- merged qkif (from xc) + v (from xt) GEMM launch ----------------
// grid 832: bid<576 -> qkif tile; else v tile.
__global__ void __launch_bounds__(256, 2) qkif_v(
    const __half* __restrict__ xc2, const __half* __restrict__ xt2,
    const __half* __restrict__ wqkif, const __half* __restrict__ wv,
    const float* __restrict__ bq, const float* __restrict__ bk,
    const float* __restrict__ bi, const float* __restrict__ bf,
    const float* __restrict__ bv,
    float* __restrict__ q, float* __restrict__ k,
    float* __restrict__ ib, float* __restrict__ fb, float* __restrict__ vb)
{
    extern __shared__ __align__(128) char dsm[];
    const int bid = blockIdx.x;
    const int tid = threadIdx.x;
    const bool isv = bid >= 576;

    int m0, n0;
    if (!isv) { m0 = (bid / 9) * MTILE; n0 = (bid % 9) * NTILE; }
    else      { int idx = bid - 576; m0 = (idx >> 2) * MTILE; n0 = (idx & 3) * NTILE; }

    gemm_core<KE_P>(isv ? xt2 : xc2, isv ? wv : wqkif, dsm, m0, n0);

    float* tile = (float*)dsm;
    const int col = tid & 127;
    const int rb  = tid >> 7;
    const int n   = n0 + col;

    if (isv) {
        const float bias = bv[n];
        for (int rr = rb; rr < 128; rr += 2)
            vb[(size_t)(m0 + rr) * 512 + n] = tile[rr * 130 + col] + bias;
    } else if (n < 512) {
        const float bias = bq[n];
        for (int rr = rb; rr < 128; rr += 2)
            q[(size_t)(m0 + rr) * 512 + n] = tile[rr * 130 + col] + bias;
    } else if (n < 1024) {
        const int nn = n - 512;
        const float bias = bk[nn];
        for (int rr = rb; rr < 128; rr += 2)
            k[(size_t)(m0 + rr) * 512 + nn] = (tile[rr * 130 + col] + bias) * 0.125f;
    } else {
        const int gi = n - 1024;
        if (gi < 16) {
            float* op = gi < 8 ? ib : fb;
            const float bias = gi < 8 ? bi[gi] : bf[gi - 8];
            const int hh = gi & 7;
            for (int rr = rb; rr < 128; rr += 2) {
                float v = tile[rr * 130 + col] + bias;
                op[(size_t)(m0 + rr) * H_ + hh] = CAP * tanhf(v * (1.0f / CAP));
            }
        }
    }
}

// ---------------- fused: skip GEMM + o GEMM + sequential recurrence ----------------
// grid 576: bid<64 -> recurrence; else GEMM tile (256 skip + 256 o).
__global__ void __launch_bounds__(256, 2) skip_o_recur(
    const __half* __restrict__ xc2, const __half* __restrict__ xt2,
    const __half* __restrict__ wskip, const __half* __restrict__ wo,
    const float* __restrict__ bskip, const float* __restrict__ bo,
    float* __restrict__ skip, float* __restrict__ ob,
    const float* __restrict__ q, const float* __restrict__ k, const float* __restrict__ v,
    const float* __restrict__ ip, const float* __restrict__ fp, float* __restrict__ hs)
{
    extern __shared__ __align__(128) char dsm[];
    const int bid = blockIdx.x;
    const int tid = threadIdx.x;

    if (bid >= 64) {
        const int idx = bid - 64;
        const bool iso = idx >= 256;
        const int t2 = idx & 255;
        const int m0 = (t2 >> 2) * MTILE;
        const int n0 = (t2 & 3) * NTILE;
        const __half* A = iso ? xt2 : xc2;
        const __half* W = iso ? wo : wskip;
        gemm_core<KE_P>(A, W, dsm, m0, n0);

        float* tile = (float*)dsm;
        const int col = tid & 127;
        const int rb  = tid >> 7;
        const int n   = n0 + col;
        const float bias = iso ? bo[n] : bskip[n];
        float* op = iso ? ob : skip;
        for (int rr = rb; rr < 128; rr += 2) {
            float x = tile[rr * 130 + col] + bias;
            if (iso) x = 1.0f / (1.0f + __expf(-x));
            op[(size_t)(m0 + rr) * 512 + n] = x;
        }
        return;
    }

    // ---- recurrence part: 64 blocks x 256 threads ----
    int bh = bid;
    int b = bh >> 3, h = bh & 7;
    int t = tid;
    int d = t & 63, quarter = t >> 6;

    __shared__ __align__(16) float q_s[64], k_s[64], v_s[64];
    __shared__ float n_s[64];
    __shared__ float num_s[256];
    __shared__ float den_s[2];

    float c[16];
    #pragma unroll
    for (int j = 0; j < 16; j++) c[j] = 0.f;
    if (t < 64) n_s[t] = 1.f;
    float m = 0.f;

    size_t gbase = (size_t)b * S_ * HID_ + (size_t)h * HD_ + d;
    size_t ifbase = (size_t)b * S_ * H_ + h;

    float qr = 0.f, kr = 0.f, vr = 0.f;
    if (t < 64) { qr = q[gbase]; kr = k[gbase]; vr = v[gbase]; }
    float ir = ip[ifbase], fr = fp[ifbase];

    for (int s = 0; s < S_; s++) {
        if (t < 64) { q_s[t] = qr; k_s[t] = kr; v_s[t] = vr; }
        float it = ir, ft = fr;
        __syncthreads();

        if (s + 1 < S_) {
            size_t off = gbase + (size_t)(s + 1) * HID_;
            if (t < 64) { qr = q[off]; kr = k[off]; vr = v[off]; }
            size_t ioff = ifbase + (size_t)(s + 1) * H_;
            ir = ip[ioff]; fr = fp[ioff];
        }

        float m_t = fmaxf(ft + m, it);
        float ie  = __expf(it - m_t);
        float fe  = __expf(ft - m_t + m);
        m = m_t;

        float ievd = ie * v_s[d];
        float np0 = 0.f, np1 = 0.f, np2 = 0.f, np3 = 0.f;
        const float4* k4 = (const float4*)(k_s + quarter * 16);
        const float4* q4 = (const float4*)(q_s + quarter * 16);
        #pragma unroll
        for (int j = 0; j < 4; j++) {
            float4 kk = k4[j], qq = q4[j];
            float c0 = fmaf(fe, c[4 * j + 0], ievd * kk.x); c[4 * j + 0] = c0; np0 = fmaf(c0, qq.x, np0);
            float c1 = fmaf(fe, c[4 * j + 1], ievd * kk.y); c[4 * j + 1] = c1; np1 = fmaf(c1, qq.y, np1);
            float c2 = fmaf(fe, c[4 * j + 2], ievd * kk.z); c[4 * j + 2] = c2; np2 = fmaf(c2, qq.z, np2);
            float c3 = fmaf(fe, c[4 * j + 3], ievd * kk.w); c[4 * j + 3] = c3; np3 = fmaf(c3, qq.w, np3);
        }
        num_s[t] = (np0 + np1) + (np2 + np3);

        float denp = 0.f;
        if (t < 64) {
            float nn = fmaf(fe, n_s[t], ie * k_s[t]);
            n_s[t] = nn;
            denp = nn * q_s[t];
        }
        #pragma unroll
        for (int o = 16; o > 0; o >>= 1) denp += __shfl_down_sync(0xffffffffu, denp, o);
        if (t < 64 && (t & 31) == 0) den_s[t >> 5] = denp;
        __syncthreads();

        if (t < 64) {
            float den = fmaxf(den_s[0] + den_s[1], 1.0f);
            hs[gbase + (size_t)s * HID_] =
                ((num_s[t] + num_s[64 + t]) + (num_s[128 + t] + num_s[192 + t])) / den;
        }
    }
}

// ---------------- prep: weight convert (blocks 0..32895) + layernorm (32896..41087) ----------------
__global__ void prep_kernel(
    const float* __restrict__ Wupl, const float* __restrict__ Wupr,
    const float* __restrict__ Wq, const float* __restrict__ Wk,
    const float* __restrict__ Wi, const float* __restrict__ Wf,
    const float* __restrict__ Wskip, const float* __restrict__ Wv,
    const float* __restrict__ Wo, const float* __restrict__ Wdn,
    const float* __restrict__ x, const float* __restrict__ lng, const float* __restrict__ lnb,
    __half* __restrict__ wup, __half* __restrict__ wqkif,
    __half* __restrict__ wskip, __half* __restrict__ wv,
    __half* __restrict__ wo, __half* __restrict__ wdn,
    __half* __restrict__ xn2)
{
    __shared__ float ps1[8], ps2[8];
    const int bid = blockIdx.x;
    const int tid = threadIdx.x;

    if (bid >= 32896) {
        // ---- layernorm: one token per block ----
        int tok = bid - 32896;
        const float4* xr = (const float4*)(x + (size_t)tok * D_);
        float4 v = xr[tid];
        float s1 = v.x + v.y + v.z + v.w;
        float s2 = v.x * v.x + v.y * v.y + v.z * v.z + v.w * v.w;
        for (int o = 16; o > 0; o >>= 1) {
            s1 += __shfl_down_sync(0xffffffffu, s1, o);
            s2 += __shfl_down_sync(0xffffffffu, s2, o);
        }
        int wid = tid >> 5, lane = tid & 31;
        if (lane == 0) { ps1[wid] = s1; ps2[wid] = s2; }
        __syncthreads();
        float S1 = 0.f, S2 = 0.f;
        #pragma unroll
        for (int w = 0; w < 8; w++) { S1 += ps1[w]; S2 += ps2[w]; }
        float mu = S1 * (1.0f / D_);
        float var = S2 * (1.0f / D_) - mu * mu;
        float r = rsqrtf(var + EPS);

        float4 gv = ((const float4*)lng)[tid];
        float4 bv = ((const float4*)lnb)[tid];
        float vals[4] = { (v.x - mu) * r * gv.x + bv.x, (v.y - mu) * r * gv.y + bv.y,
                          (v.z - mu) * r * gv.z + bv.z, (v.w - mu) * r * gv.w + bv.w };
        __half h[4], l[4];
        #pragma unroll
        for (int i = 0; i < 4; i++) split2h(vals[i], h[i], l[i]);
        size_t base = (size_t)tok * KE_XN + tid * 4;
        *(__half2*)(xn2 + base)            = __half2(h[0], h[1]);
        *(__half2*)(xn2 + base + 2)        = __half2(h[2], h[3]);
        *(__half2*)(xn2 + base + 1024)     = __half2(l[0], l[1]);
        *(__half2*)(xn2 + base + 1024 + 2) = __half2(l[2], l[3]);
        return;
    }

    int idx = bid * 256 + tid;
    const float* src; __half* dst; int K, KE, rowOff, local;
    if      (idx < 2097152) { src = Wupl;  dst = wup;   K = 1024; KE = KE_XN; rowOff = 0;    local = idx; }
    else if (idx < 2621440) { src = Wupr;  dst = wup;   K = 1024; KE = KE_XN; rowOff = 2048; local = idx - 2097152; }
    else if (idx < 3670016) { src = Wq;    dst = wqkif; K = 2048; KE = KE_P;  rowOff = 0;    local = idx - 2621440; }
    else if (idx < 4718592) { src = Wk;    dst = wqkif; K = 2048; KE = KE_P;  rowOff = 512;  local = idx - 3670016; }
    else if (idx < 4734976) { src = Wi;    dst = wqkif; K = 2048; KE = KE_P;  rowOff = 1024; local = idx - 4718592; }
    else if (idx < 4751360) { src = Wf;    dst = wqkif; K = 2048; KE = KE_P;  rowOff = 1032; local = idx - 4734976; }
    else if (idx < 5799936) { src = Wskip; dst = wskip; K = 2048; KE = KE_P;  rowOff = 0;    local = idx - 4751360; }
    else if (idx < 6848512) { src = Wv;    dst = wv;    K = 2048; KE = KE_P;  rowOff = 0;    local = idx - 5799936; }
    else if (idx < 7897088) { src = Wo;    dst = wo;    K = 2048; KE = KE_P;  rowOff = 0;    local = idx - 6848512; }
    else if (idx < 8421376) { src = Wdn;   dst = wdn;   K = 512;  KE = KE_UB; rowOff = 0;    local = idx - 7897088; }
    else return;
    int r = local / K, k = local - r * K;
    __half hi = __float2half_rn(src[local]);
    size_t b = (size_t)(rowOff + r) * KE + k;
    dst[b] = hi; dst[b + K] = hi;        // W = [hi | hi]; A carries [hi | lo]
}

// ---------------- causal feature conv + SiLU: xt2 -> xc2 ----------------
__global__ void conv_silu_kernel(const __half* __restrict__ xt2,
                                 const float* __restrict__ w, const float* __restrict__ cb,
                                 __half* __restrict__ xc2)
{
    __shared__ float row[P_];
    int tok = blockIdx.x;
    int tid = threadIdx.x;        // 256
    const __half2* hi2 = (const __half2*)(xt2 + (size_t)tok * 4096);
    const __half2* lo2 = (const __half2*)(xt2 + (size_t)tok * 4096 + 2048);
    #pragma unroll
    for (int i = 0; i < 4; i++) {
        int idx = tid + i * 256;
        __half2 hp = hi2[idx], lp = lo2[idx];
        row[2 * idx]     = __half2float(hp.x) + __half2float(lp.x);
        row[2 * idx + 1] = __half2float(hp.y) + __half2float(lp.y);
    }
    __syncthreads();

    float w0 = w[0], w1 = w[1], w2 = w[2], w3 = w[3];
    float bb = cb[0];
    __half h[8], l[8];
    #pragma unroll
    for (int i = 0; i < 8; i++) {
        int p = tid * 8 + i;
        float x3 = row[p];
        float x2 = (p >= 1) ? row[p - 1] : 0.f;
        float x1 = (p >= 2) ? row[p - 2] : 0.f;
        float x0 = (p >= 3) ? row[p - 3] : 0.f;
        float v = bb + w0 * x0 + w1 * x1 + w2 * x2 + w3 * x3;
        v = v / (1.0f + __expf(-v));
        split2h(v, h[i], l[i]);
    }
    size_t base = (size_t)tok * 4096 + tid * 8;
    #pragma unroll
    for (int i = 0; i < 4; i++) {
        *(__half2*)(xc2 + base + 2 * i)        = __half2(h[2 * i], h[2 * i + 1]);
        *(__half2*)(xc2 + base + 2048 + 2 * i) = __half2(l[2 * i], l[2 * i + 1]);
    }
}

// ---------------- mix: o*hs, per-head LN, + skip, * silu(r_t) -> ub dual ----------------
__global__ void mix_kernel(const float* __restrict__ hs, const float* __restrict__ o,
                           const float* __restrict__ skip, const float* __restrict__ rt,
                           const float* __restrict__ mhg, const float* __restrict__ mhb,
                           __half* __restrict__ ub2)
{
    int tok = blockIdx.x;
    int tid = threadIdx.x;          // 512
    int head = tid >> 6;
    size_t idx = (size_t)tok * HID_ + tid;

    float val = o[idx] * hs[idx];
    float s1 = val, s2 = val * val;
    for (int off = 16; off > 0; off >>= 1) {
        s1 += __shfl_down_sync(0xffffffffu, s1, off);
        s2 += __shfl_down_sync(0xffffffffu, s2, off);
    }
    __shared__ float ps1[16], ps2[16];
    int wid = tid >> 5, lane = tid & 31;
    if (lane == 0) { ps1[wid] = s1; ps2[wid] = s2; }
    __syncthreads();
    float S1 = ps1[head * 2] + ps1[head * 2 + 1];
    float S2 = ps2[head * 2] + ps2[head * 2 + 1];
    float mu = S1 * (1.0f / HD_);
    float var = S2 * (1.0f / HD_) - mu * mu;
    float r = rsqrtf(var + EPS);

    float hn = (val - mu) * r * mhg[tid] + mhb[tid];
    float rv = rt[idx];
    float u = (hn + skip[idx]) * (rv / (1.0f + __expf(-rv)));

    __half hi, lo;
    split2h(u, hi, lo);
    size_t b = (size_t)tok * KE_UB + tid;
    ub2[b] = hi; ub2[b + 512] = lo;
}

// ---------------- host launcher ----------------
extern "C" void kernel_launch(void* const* d_in, const int* in_sizes, int n_in,
                              void* d_out, int out_size)
{
    const float* x      = (const float*)d_in[0];
    const float* ln_g   = (const float*)d_in[1];
    const float* ln_b   = (const float*)d_in[2];
    const float* mh_g   = (const float*)d_in[3];
    const float* mh_b   = (const float*)d_in[4];
    const float* W_up_l = (const float*)d_in[5];
    const float* b_up_l = (const float*)d_in[6];
    const float* W_up_r = (const float*)d_in[7];
    const float* b_up_r = (const float*)d_in[8];
    const float* W_down = (const float*)d_in[9];
    const float* b_down = (const float*)d_in[10];
    const float* conv_w = (const float*)d_in[11];
    const float* conv_b = (const float*)d_in[12];
    const float* W_skip = (const float*)d_in[13];
    const float* b_skip = (const float*)d_in[14];
    const float* W_i    = (const float*)d_in[15];
    const float* b_i    = (const float*)d_in[16];
    const float* W_f    = (const float*)d_in[17];
    const float* b_f    = (const float*)d_in[18];
    const float* W_o    = (const float*)d_in[19];
    const float* b_o    = (const float*)d_in[20];
    const float* W_q    = (const float*)d_in[21];
    const float* b_q    = (const float*)d_in[22];
    const float* W_k    = (const float*)d_in[23];
    const float* b_k    = (const float*)d_in[24];
    const float* W_v    = (const float*)d_in[25];
    const float* b_v    = (const float*)d_in[26];
    float* out = (float*)d_out;

    float *rt, *skip, *qb, *kb, *vb, *ob, *ib, *fb, *hsb;
    __half *xn2, *xt2, *xc2, *ub2, *wup, *wqkif, *wskip, *wv, *wo, *wdn;
    cudaGetSymbolAddress((void**)&rt,    g_rt);
    cudaGetSymbolAddress((void**)&skip,  g_skip);
    cudaGetSymbolAddress((void**)&qb,    g_q);
    cudaGetSymbolAddress((void**)&kb,    g_k);
    cudaGetSymbolAddress((void**)&vb,    g_v);
    cudaGetSymbolAddress((void**)&ob,    g_o);
    cudaGetSymbolAddress((void**)&ib,    g_i);
    cudaGetSymbolAddress((void**)&fb,    g_f);
    cudaGetSymbolAddress((void**)&hsb,   g_hs);
    cudaGetSymbolAddress((void**)&xn2,   g_xn2);
    cudaGetSymbolAddress((void**)&xt2,   g_xt2);
    cudaGetSymbolAddress((void**)&xc2,   g_xc2);
    cudaGetSymbolAddress((void**)&ub2,   g_ub2);
    cudaGetSymbolAddress((void**)&wup,   g_wup);
    cudaGetSymbolAddress((void**)&wqkif, g_wqkif);
    cudaGetSymbolAddress((void**)&wskip, g_wskip);
    cudaGetSymbolAddress((void**)&wv,    g_wv);
    cudaGetSymbolAddress((void**)&wo,    g_wo);
    cudaGetSymbolAddress((void**)&wdn,   g_wdn);

    cudaFuncSetAttribute((const void*)gemm_mma<0, KE_XN>, cudaFuncAttributeMaxDynamicSharedMemorySize, GSMEM);
    cudaFuncSetAttribute((const void*)gemm_mma<4, KE_UB>, cudaFuncAttributeMaxDynamicSharedMemorySize, GSMEM);
    cudaFuncSetAttribute((const void*)qkif_v,             cudaFuncAttributeMaxDynamicSharedMemorySize, GSMEM);
    cudaFuncSetAttribute((const void*)skip_o_recur,       cudaFuncAttributeMaxDynamicSharedMemorySize, GSMEM);

    // [0] merged weight conversion + layernorm (wqkif rows 1040..1151 stay zero)
    prep_kernel<<<41088, 256>>>(W_up_l, W_up_r, W_q, W_k, W_i, W_f, W_skip, W_v, W_o, W_down,
                                x, ln_g, ln_b,
                                wup, wqkif, wskip, wv, wo, wdn, xn2);

    // [1] merged up projection: xt2 | rt
    {
        dim3 grid(2560 / NTILE, TOK / MTILE);
        gemm_mma<0, KE_XN><<<grid, 256, GSMEM>>>(xn2, wup, b_up_l, b_up_r,
                                                 nullptr, (float*)xt2, rt);
    }

    // [2] causal conv + silu
    conv_silu_kernel<<<TOK, 256>>>(xt2, conv_w, conv_b, xc2);

    // [3] merged q|k|i|f (xc) + v (xt) — one launch, one tail
    qkif_v<<<832, 256, GSMEM>>>(xc2, xt2, wqkif, wv, b_q, b_k, b_i, b_f, b_v,
                                qb, kb, ib, fb, vb);

    // [4] fused: recurrence (64 blocks first) + skip GEMM + o GEMM
    skip_o_recur<<<576, 256, GSMEM>>>(xc2, xt2, wskip, wo, b_skip, b_o, skip, ob,
                                      qb, kb, vb, ib, fb, hsb);

    // [5] mix -> ub dual
    mix_kernel<<<TOK, 512>>>(hsb, ob, skip, rt, mh_g, mh_b, ub2);

    // [6] down projection + bias + residual
    {
        dim3 grid(1024 / NTILE, TOK / MTILE);
        gemm_mma<4, KE_UB><<<grid, 256, GSMEM>>>(ub2, wdn, b_down, nullptr,
                                                 x, out, nullptr);
    }
}

// round 17
// speedup vs baseline: 1.3557x; 1.1116x over previous
#include <cuda_runtime.h>
#include <cuda_fp16.h>
#include <cstdint>
#include <cstddef>

// ---------------- problem constants ----------------
#define B_  8
#define S_  1024
#define D_  1024
#define H_  8
#define HD_ 64
#define HID_ 512
#define P_  2048
#define TOK (B_ * S_)
#define EPS 1e-6f
#define CAP 15.0f

// fp16 2-term K widths (A=[hi|lo], W=[hi|hi])
#define KE_XN 2048
#define KE_P  4096
#define KE_UB 1024

// ---------------- static device scratch ----------------
__device__ __align__(128) float g_rt  [(size_t)TOK * HID_];
__device__ __align__(128) float g_skip[(size_t)TOK * HID_];
__device__ __align__(128) float g_q   [(size_t)TOK * HID_];
__device__ __align__(128) float g_k   [(size_t)TOK * HID_];
__device__ __align__(128) float g_v   [(size_t)TOK * HID_];
__device__ __align__(128) float g_o   [(size_t)TOK * HID_];
__device__ __align__(128) float g_i   [(size_t)TOK * H_];
__device__ __align__(128) float g_f   [(size_t)TOK * H_];
__device__ __align__(128) float g_hs  [(size_t)TOK * HID_];

__device__ __align__(128) __half g_xn2 [(size_t)TOK * KE_XN];
__device__ __align__(128) __half g_xt2 [(size_t)TOK * KE_P];
__device__ __align__(128) __half g_xc2 [(size_t)TOK * KE_P];
__device__ __align__(128) __half g_ub2 [(size_t)TOK * KE_UB];
__device__ __align__(128) __half g_wup  [(size_t)2560 * KE_XN];  // up_l|up_r
__device__ __align__(128) __half g_wqkif[(size_t)1152 * KE_P];   // q|k|i|f|pad0
__device__ __align__(128) __half g_wskip[(size_t)512  * KE_P];
__device__ __align__(128) __half g_wv   [(size_t)512  * KE_P];
__device__ __align__(128) __half g_wo   [(size_t)512  * KE_P];
__device__ __align__(128) __half g_wdn  [(size_t)1024 * KE_UB];

// ---------------- mma.sync GEMM config ----------------
#define MTILE 128
#define NTILE 128
#define BKE   64
#define ROWB  144
#define STAGE_A (MTILE * ROWB)
#define STAGE_B (NTILE * ROWB)
#define STAGE_BYTES (STAGE_A + STAGE_B)
#define GSMEM (2 * STAGE_BYTES)       // 73728; also holds 128x130 fp32 epilogue tile

__device__ __forceinline__ uint32_t smem_u32(const void* p) {
    uint32_t a;
    asm("{ .reg .u64 t; cvta.to.shared.u64 t, %1; cvt.u32.u64 %0, t; }" : "=r"(a) : "l"(p));
    return a;
}

__device__ __forceinline__ void ldsm4(uint32_t& r0, uint32_t& r1, uint32_t& r2, uint32_t& r3,
                                      uint32_t addr) {
    asm volatile("ldmatrix.sync.aligned.m8n8.x4.shared.b16 {%0,%1,%2,%3}, [%4];"
                 : "=r"(r0), "=r"(r1), "=r"(r2), "=r"(r3) : "r"(addr));
}

__device__ __forceinline__ void mma_f16(float& c0, float& c1, float& c2, float& c3,
                                        uint32_t a0, uint32_t a1, uint32_t a2, uint32_t a3,
                                        uint32_t b0, uint32_t b1) {
    asm volatile(
        "mma.sync.aligned.m16n8k16.row.col.f32.f16.f16.f32 "
        "{%0,%1,%2,%3}, {%4,%5,%6,%7}, {%8,%9}, {%0,%1,%2,%3};"
        : "+f"(c0), "+f"(c1), "+f"(c2), "+f"(c3)
        : "r"(a0), "r"(a1), "r"(a2), "r"(a3), "r"(b0), "r"(b1));
}

__device__ __forceinline__ void split2h(float v, __half& hi, __half& lo) {
    hi = __float2half_rn(v);
    lo = __float2half_rn(v - __half2float(hi));
}

// ---------------- shared GEMM core: mainloop + acc -> smem tile (pitch 130) ----------------
template<int KE>
__device__ __forceinline__ void gemm_core(
    const __half* __restrict__ A, const __half* __restrict__ W,
    char* dsm, int m0, int n0)
{
    const uint32_t sbase = smem_u32(dsm);
    const int tid = threadIdx.x;
    const int wid = tid >> 5, lane = tid & 31;
    const int warp_m = wid >> 1;
    const int warp_n = wid & 1;

    constexpr int NS = KE / BKE;

    auto load_stage = [&](int ss, int buf) {
        const uint32_t sa = sbase + buf * STAGE_BYTES;
        #pragma unroll
        for (int j = 0; j < 4; j++) {
            int cid = tid + j * 256;
            int r = cid >> 3, cg = cid & 7;
            const char* gA = (const char*)A + ((size_t)(m0 + r) * KE + ss * BKE) * 2 + cg * 16;
            asm volatile("cp.async.cg.shared.global [%0], [%1], 16;"
                         :: "r"(sa + r * ROWB + cg * 16), "l"(gA));
            const char* gB = (const char*)W + ((size_t)(n0 + r) * KE + ss * BKE) * 2 + cg * 16;
            asm volatile("cp.async.cg.shared.global [%0], [%1], 16;"
                         :: "r"(sa + STAGE_A + r * ROWB + cg * 16), "l"(gB));
        }
    };

    float acc[2][8][4];
    #pragma unroll
    for (int i = 0; i < 2; i++)
        #pragma unroll
        for (int j = 0; j < 8; j++)
            #pragma unroll
            for (int c = 0; c < 4; c++) acc[i][j][c] = 0.f;

    load_stage(0, 0);
    asm volatile("cp.async.commit_group;");

    const int a_row = lane & 15;
    const int a_kh  = lane >> 4;
    const int b_row = (lane & 7) | ((lane >> 4) << 3);
    const int b_kh  = (lane >> 3) & 1;

    #pragma unroll 2
    for (int s = 0; s < NS; s++) {
        const int buf = s & 1;
        asm volatile("cp.async.wait_group 0;");
        __syncthreads();

        if (s + 1 < NS) load_stage(s + 1, (s + 1) & 1);
        asm volatile("cp.async.commit_group;");

        const uint32_t sa = sbase + buf * STAGE_BYTES;
        const uint32_t sb = sa + STAGE_A;

        #pragma unroll
        for (int ks = 0; ks < 4; ks++) {
            uint32_t afr[2][4];
            #pragma unroll
            for (int mt = 0; mt < 2; mt++) {
                uint32_t addr = sa + (warp_m * 32 + mt * 16 + a_row) * ROWB
                              + ks * 32 + a_kh * 16;
                ldsm4(afr[mt][0], afr[mt][1], afr[mt][2], afr[mt][3], addr);
            }
            uint32_t bfr[4][4];
            #pragma unroll
            for (int np = 0; np < 4; np++) {
                uint32_t addr = sb + (warp_n * 64 + np * 16 + b_row) * ROWB
                              + ks * 32 + b_kh * 16;
                ldsm4(bfr[np][0], bfr[np][1], bfr[np][2], bfr[np][3], addr);
            }
            #pragma unroll
            for (int mt = 0; mt < 2; mt++)
                #pragma unroll
                for (int nt = 0; nt < 8; nt++)
                    mma_f16(acc[mt][nt][0], acc[mt][nt][1], acc[mt][nt][2], acc[mt][nt][3],
                            afr[mt][0], afr[mt][1], afr[mt][2], afr[mt][3],
                            bfr[nt >> 1][(nt & 1) * 2], bfr[nt >> 1][(nt & 1) * 2 + 1]);
        }
    }

    __syncthreads();
    float* tile = (float*)dsm;
    const int er = lane >> 2;
    const int ec = (lane & 3) * 2;
    #pragma unroll
    for (int mt = 0; mt < 2; mt++) {
        #pragma unroll
        for (int nt = 0; nt < 8; nt++) {
            int rl = warp_m * 32 + mt * 16 + er;
            int cl = warp_n * 64 + nt * 8 + ec;
            tile[rl * 130 + cl]           = acc[mt][nt][0];
            tile[rl * 130 + cl + 1]       = acc[mt][nt][1];
            tile[(rl + 8) * 130 + cl]     = acc[mt][nt][2];
            tile[(rl + 8) * 130 + cl + 1] = acc[mt][nt][3];
        }
    }
    __syncthreads();
}

// MODE: 0 UP (n<2048: xt2 dual | n>=2048: rt)   4 DOWN (+bias+resid)
template<int MODE, int KE>
__global__ void __launch_bounds__(256, 2) gemm_mma(
    const __half* __restrict__ A, const __half* __restrict__ W,
    const float* __restrict__ b0, const float* __restrict__ b1,
    const float* __restrict__ resid,
    float* __restrict__ o0, float* __restrict__ o1)
{
    extern __shared__ __align__(128) char dsm[];
    const int m0 = blockIdx.y * MTILE;
    const int n0 = blockIdx.x * NTILE;
    gemm_core<KE>(A, W, dsm, m0, n0);

    float* tile = (float*)dsm;
    const int tid = threadIdx.x;
    const int col = tid & 127;
    const int rb  = tid >> 7;
    const int n   = n0 + col;

    if (MODE == 0) {
        if (n < 2048) {
            const float bias = b0[n];
            __half* xt2 = (__half*)o0;
            for (int rr = rb; rr < 128; rr += 2) {
                float v = tile[rr * 130 + col] + bias;
                __half hi, lo; split2h(v, hi, lo);
                size_t base = (size_t)(m0 + rr) * 4096 + n;
                xt2[base] = hi; xt2[base + 2048] = lo;
            }
        } else {
            const int nn = n - 2048;
            const float bias = b1[nn];
            for (int rr = rb; rr < 128; rr += 2)
                o1[(size_t)(m0 + rr) * 512 + nn] = tile[rr * 130 + col] + bias;
        }
    } else {
        const float bias = b0[n];
        for (int rr = rb; rr < 128; rr += 2) {
            size_t gi = (size_t)(m0 + rr) * 1024 + n;
            o0[gi] = tile[rr * 130 + col] + bias + resid[gi];
        }
    }
}

// ---------------- merged qkif (from xc) + v (from xt) GEMM launch ----------------
// grid 832: bid<576 -> qkif tile; else v tile.
__global__ void __launch_bounds__(256, 2) qkif_v(
    const __half* __restrict__ xc2, const __half* __restrict__ xt2,
    const __half* __restrict__ wqkif, const __half* __restrict__ wv,
    const float* __restrict__ bq, const float* __restrict__ bk,
    const float* __restrict__ bi, const float* __restrict__ bf,
    const float* __restrict__ bv,
    float* __restrict__ q, float* __restrict__ k,
    float* __restrict__ ib, float* __restrict__ fb, float* __restrict__ vb)
{
    extern __shared__ __align__(128) char dsm[];
    const int bid = blockIdx.x;
    const int tid = threadIdx.x;
    const bool isv = bid >= 576;

    int m0, n0;
    if (!isv) { m0 = (bid / 9) * MTILE; n0 = (bid % 9) * NTILE; }
    else      { int idx = bid - 576; m0 = (idx >> 2) * MTILE; n0 = (idx & 3) * NTILE; }

    gemm_core<KE_P>(isv ? xt2 : xc2, isv ? wv : wqkif, dsm, m0, n0);

    float* tile = (float*)dsm;
    const int col = tid & 127;
    const int rb  = tid >> 7;
    const int n   = n0 + col;

    if (isv) {
        const float bias = bv[n];
        for (int rr = rb; rr < 128; rr += 2)
            vb[(size_t)(m0 + rr) * 512 + n] = tile[rr * 130 + col] + bias;
    } else if (n < 512) {
        const float bias = bq[n];
        for (int rr = rb; rr < 128; rr += 2)
            q[(size_t)(m0 + rr) * 512 + n] = tile[rr * 130 + col] + bias;
    } else if (n < 1024) {
        const int nn = n - 512;
        const float bias = bk[nn];
        for (int rr = rb; rr < 128; rr += 2)
            k[(size_t)(m0 + rr) * 512 + nn] = (tile[rr * 130 + col] + bias) * 0.125f;
    } else {
        const int gi = n - 1024;
        if (gi < 16) {
            float* op = gi < 8 ? ib : fb;
            const float bias = gi < 8 ? bi[gi] : bf[gi - 8];
            const int hh = gi & 7;
            for (int rr = rb; rr < 128; rr += 2) {
                float v = tile[rr * 130 + col] + bias;
                op[(size_t)(m0 + rr) * H_ + hh] = CAP * tanhf(v * (1.0f / CAP));
            }
        }
    }
}

// ---------------- fused: skip GEMM + o GEMM + sequential recurrence (1 bar/step) ----------------
// grid 576: bid<64 -> recurrence; else GEMM tile (256 skip + 256 o).
__global__ void __launch_bounds__(256, 2) skip_o_recur(
    const __half* __restrict__ xc2, const __half* __restrict__ xt2,
    const __half* __restrict__ wskip, const __half* __restrict__ wo,
    const float* __restrict__ bskip, const float* __restrict__ bo,
    float* __restrict__ skip, float* __restrict__ ob,
    const float* __restrict__ q, const float* __restrict__ k, const float* __restrict__ v,
    const float* __restrict__ ip, const float* __restrict__ fp, float* __restrict__ hs)
{
    extern __shared__ __align__(128) char dsm[];
    const int bid = blockIdx.x;
    const int tid = threadIdx.x;

    if (bid >= 64) {
        const int idx = bid - 64;
        const bool iso = idx >= 256;
        const int t2 = idx & 255;
        const int m0 = (t2 >> 2) * MTILE;
        const int n0 = (t2 & 3) * NTILE;
        const __half* A = iso ? xt2 : xc2;
        const __half* W = iso ? wo : wskip;
        gemm_core<KE_P>(A, W, dsm, m0, n0);

        float* tile = (float*)dsm;
        const int col = tid & 127;
        const int rb  = tid >> 7;
        const int n   = n0 + col;
        const float bias = iso ? bo[n] : bskip[n];
        float* op = iso ? ob : skip;
        for (int rr = rb; rr < 128; rr += 2) {
            float x = tile[rr * 130 + col] + bias;
            if (iso) x = 1.0f / (1.0f + __expf(-x));
            op[(size_t)(m0 + rr) * 512 + n] = x;
        }
        return;
    }

    // ---- recurrence: 64 blocks x 256 threads, double-buffered, ONE bar per step ----
    int bh = bid;
    int b = bh >> 3, h = bh & 7;
    int t = tid;
    int d = t & 63, quarter = t >> 6;
    int lane = t & 31;

    __shared__ __align__(16) float q_s[2][64], k_s[2][64], v_s[2][64];
    __shared__ float num_s[2][256];
    __shared__ float den_s[2][2];

    float c[16];
    #pragma unroll
    for (int j = 0; j < 16; j++) c[j] = 0.f;
    float nst = 1.f;                    // n-state, valid for t < 64
    float m = 0.f;

    size_t gbase = (size_t)b * S_ * HID_ + (size_t)h * HD_ + d;
    size_t ifbase = (size_t)b * S_ * H_ + h;

    float qr = 0.f, kr = 0.f, vr = 0.f;
    if (t < 64) { qr = q[gbase]; kr = k[gbase]; vr = v[gbase]; }
    float ir = ip[ifbase], fr = fp[ifbase];

    for (int s = 0; s < S_; s++) {
        const int buf = s & 1;
        if (t < 64) { q_s[buf][t] = qr; k_s[buf][t] = kr; v_s[buf][t] = vr; }
        float it = ir, ft = fr;
        __syncthreads();               // publishes step-s inputs AND step-(s-1) num/den

        // prefetch step s+1
        if (s + 1 < S_) {
            size_t off = gbase + (size_t)(s + 1) * HID_;
            if (t < 64) { qr = q[off]; kr = k[off]; vr = v[off]; }
            size_t ioff = ifbase + (size_t)(s + 1) * H_;
            ir = ip[ioff]; fr = fp[ioff];
        }

        // deferred output for step s-1 (reads other parity; race-free via the bar above)
        if (s > 0 && t < 64) {
            const int pb = buf ^ 1;
            float den = fmaxf(den_s[pb][0] + den_s[pb][1], 1.0f);
            hs[gbase + (size_t)(s - 1) * HID_] =
                ((num_s[pb][t] + num_s[pb][64 + t]) + (num_s[pb][128 + t] + num_s[pb][192 + t])) / den;
        }

        float m_t = fmaxf(ft + m, it);
        float ie  = __expf(it - m_t);
        float fe  = __expf(ft - m_t + m);
        m = m_t;

        float ievd = ie * v_s[buf][d];
        float np0 = 0.f, np1 = 0.f, np2 = 0.f, np3 = 0.f;
        const float4* k4 = (const float4*)(k_s[buf] + quarter * 16);
        const float4* q4 = (const float4*)(q_s[buf] + quarter * 16);
        #pragma unroll
        for (int j = 0; j < 4; j++) {
            float4 kk = k4[j], qq = q4[j];
            float c0 = fmaf(fe, c[4 * j + 0], ievd * kk.x); c[4 * j + 0] = c0; np0 = fmaf(c0, qq.x, np0);
            float c1 = fmaf(fe, c[4 * j + 1], ievd * kk.y); c[4 * j + 1] = c1; np1 = fmaf(c1, qq.y, np1);
            float c2 = fmaf(fe, c[4 * j + 2], ievd * kk.z); c[4 * j + 2] = c2; np2 = fmaf(c2, qq.z, np2);
            float c3 = fmaf(fe, c[4 * j + 3], ievd * kk.w); c[4 * j + 3] = c3; np3 = fmaf(c3, qq.w, np3);
        }
        num_s[buf][t] = (np0 + np1) + (np2 + np3);

        if (t < 64) {
            nst = fmaf(fe, nst, ie * k_s[buf][t]);
            float denp = nst * q_s[buf][t];
            #pragma unroll
            for (int o = 16; o > 0; o >>= 1) denp += __shfl_down_sync(0xffffffffu, denp, o);
            if (lane == 0) den_s[buf][t >> 5] = denp;
        }
    }

    // final output for step S-1
    __syncthreads();
    if (t < 64) {
        const int pb = (S_ - 1) & 1;
        float den = fmaxf(den_s[pb][0] + den_s[pb][1], 1.0f);
        hs[gbase + (size_t)(S_ - 1) * HID_] =
            ((num_s[pb][t] + num_s[pb][64 + t]) + (num_s[pb][128 + t] + num_s[pb][192 + t])) / den;
    }
}

// ---------------- prep: weight convert (blocks 0..32895) + layernorm (32896..41087) ----------------
__global__ void prep_kernel(
    const float* __restrict__ Wupl, const float* __restrict__ Wupr,
    const float* __restrict__ Wq, const float* __restrict__ Wk,
    const float* __restrict__ Wi, const float* __restrict__ Wf,
    const float* __restrict__ Wskip, const float* __restrict__ Wv,
    const float* __restrict__ Wo, const float* __restrict__ Wdn,
    const float* __restrict__ x, const float* __restrict__ lng, const float* __restrict__ lnb,
    __half* __restrict__ wup, __half* __restrict__ wqkif,
    __half* __restrict__ wskip, __half* __restrict__ wv,
    __half* __restrict__ wo, __half* __restrict__ wdn,
    __half* __restrict__ xn2)
{
    __shared__ float ps1[8], ps2[8];
    const int bid = blockIdx.x;
    const int tid = threadIdx.x;

    if (bid >= 32896) {
        // ---- layernorm: one token per block ----
        int tok = bid - 32896;
        const float4* xr = (const float4*)(x + (size_t)tok * D_);
        float4 v = xr[tid];
        float s1 = v.x + v.y + v.z + v.w;
        float s2 = v.x * v.x + v.y * v.y + v.z * v.z + v.w * v.w;
        for (int o = 16; o > 0; o >>= 1) {
            s1 += __shfl_down_sync(0xffffffffu, s1, o);
            s2 += __shfl_down_sync(0xffffffffu, s2, o);
        }
        int wid = tid >> 5, lane = tid & 31;
        if (lane == 0) { ps1[wid] = s1; ps2[wid] = s2; }
        __syncthreads();
        float S1 = 0.f, S2 = 0.f;
        #pragma unroll
        for (int w = 0; w < 8; w++) { S1 += ps1[w]; S2 += ps2[w]; }
        float mu = S1 * (1.0f / D_);
        float var = S2 * (1.0f / D_) - mu * mu;
        float r = rsqrtf(var + EPS);

        float4 gv = ((const float4*)lng)[tid];
        float4 bv = ((const float4*)lnb)[tid];
        float vals[4] = { (v.x - mu) * r * gv.x + bv.x, (v.y - mu) * r * gv.y + bv.y,
                          (v.z - mu) * r * gv.z + bv.z, (v.w - mu) * r * gv.w + bv.w };
        __half h[4], l[4];
        #pragma unroll
        for (int i = 0; i < 4; i++) split2h(vals[i], h[i], l[i]);
        size_t base = (size_t)tok * KE_XN + tid * 4;
        *(__half2*)(xn2 + base)            = __half2(h[0], h[1]);
        *(__half2*)(xn2 + base + 2)        = __half2(h[2], h[3]);
        *(__half2*)(xn2 + base + 1024)     = __half2(l[0], l[1]);
        *(__half2*)(xn2 + base + 1024 + 2) = __half2(l[2], l[3]);
        return;
    }

    int idx = bid * 256 + tid;
    const float* src; __half* dst; int K, KE, rowOff, local;
    if      (idx < 2097152) { src = Wupl;  dst = wup;   K = 1024; KE = KE_XN; rowOff = 0;    local = idx; }
    else if (idx < 2621440) { src = Wupr;  dst = wup;   K = 1024; KE = KE_XN; rowOff = 2048; local = idx - 2097152; }
    else if (idx < 3670016) { src = Wq;    dst = wqkif; K = 2048; KE = KE_P;  rowOff = 0;    local = idx - 2621440; }
    else if (idx < 4718592) { src = Wk;    dst = wqkif; K = 2048; KE = KE_P;  rowOff = 512;  local = idx - 3670016; }
    else if (idx < 4734976) { src = Wi;    dst = wqkif; K = 2048; KE = KE_P;  rowOff = 1024; local = idx - 4718592; }
    else if (idx < 4751360) { src = Wf;    dst = wqkif; K = 2048; KE = KE_P;  rowOff = 1032; local = idx - 4734976; }
    else if (idx < 5799936) { src = Wskip; dst = wskip; K = 2048; KE = KE_P;  rowOff = 0;    local = idx - 4751360; }
    else if (idx < 6848512) { src = Wv;    dst = wv;    K = 2048; KE = KE_P;  rowOff = 0;    local = idx - 5799936; }
    else if (idx < 7897088) { src = Wo;    dst = wo;    K = 2048; KE = KE_P;  rowOff = 0;    local = idx - 6848512; }
    else if (idx < 8421376) { src = Wdn;   dst = wdn;   K = 512;  KE = KE_UB; rowOff = 0;    local = idx - 7897088; }
    else return;
    int r = local / K, k = local - r * K;
    __half hi = __float2half_rn(src[local]);
    size_t b = (size_t)(rowOff + r) * KE + k;
    dst[b] = hi; dst[b + K] = hi;        // W = [hi | hi]; A carries [hi | lo]
}

// ---------------- causal feature conv + SiLU: xt2 -> xc2 ----------------
__global__ void conv_silu_kernel(const __half* __restrict__ xt2,
                                 const float* __restrict__ w, const float* __restrict__ cb,
                                 __half* __restrict__ xc2)
{
    __shared__ float row[P_];
    int tok = blockIdx.x;
    int tid = threadIdx.x;        // 256
    const __half2* hi2 = (const __half2*)(xt2 + (size_t)tok * 4096);
    const __half2* lo2 = (const __half2*)(xt2 + (size_t)tok * 4096 + 2048);
    #pragma unroll
    for (int i = 0; i < 4; i++) {
        int idx = tid + i * 256;
        __half2 hp = hi2[idx], lp = lo2[idx];
        row[2 * idx]     = __half2float(hp.x) + __half2float(lp.x);
        row[2 * idx + 1] = __half2float(hp.y) + __half2float(lp.y);
    }
    __syncthreads();

    float w0 = w[0], w1 = w[1], w2 = w[2], w3 = w[3];
    float bb = cb[0];
    __half h[8], l[8];
    #pragma unroll
    for (int i = 0; i < 8; i++) {
        int p = tid * 8 + i;
        float x3 = row[p];
        float x2 = (p >= 1) ? row[p - 1] : 0.f;
        float x1 = (p >= 2) ? row[p - 2] : 0.f;
        float x0 = (p >= 3) ? row[p - 3] : 0.f;
        float v = bb + w0 * x0 + w1 * x1 + w2 * x2 + w3 * x3;
        v = v / (1.0f + __expf(-v));
        split2h(v, h[i], l[i]);
    }
    size_t base = (size_t)tok * 4096 + tid * 8;
    #pragma unroll
    for (int i = 0; i < 4; i++) {
        *(__half2*)(xc2 + base + 2 * i)        = __half2(h[2 * i], h[2 * i + 1]);
        *(__half2*)(xc2 + base + 2048 + 2 * i) = __half2(l[2 * i], l[2 * i + 1]);
    }
}

// ---------------- mix: o*hs, per-head LN, + skip, * silu(r_t) -> ub dual ----------------
__global__ void mix_kernel(const float* __restrict__ hs, const float* __restrict__ o,
                           const float* __restrict__ skip, const float* __restrict__ rt,
                           const float* __restrict__ mhg, const float* __restrict__ mhb,
                           __half* __restrict__ ub2)
{
    int tok = blockIdx.x;
    int tid = threadIdx.x;          // 512
    int head = tid >> 6;
    size_t idx = (size_t)tok * HID_ + tid;

    float val = o[idx] * hs[idx];
    float s1 = val, s2 = val * val;
    for (int off = 16; off > 0; off >>= 1) {
        s1 += __shfl_down_sync(0xffffffffu, s1, off);
        s2 += __shfl_down_sync(0xffffffffu, s2, off);
    }
    __shared__ float ps1[16], ps2[16];
    int wid = tid >> 5, lane = tid & 31;
    if (lane == 0) { ps1[wid] = s1; ps2[wid] = s2; }
    __syncthreads();
    float S1 = ps1[head * 2] + ps1[head * 2 + 1];
    float S2 = ps2[head * 2] + ps2[head * 2 + 1];
    float mu = S1 * (1.0f / HD_);
    float var = S2 * (1.0f / HD_) - mu * mu;
    float r = rsqrtf(var + EPS);

    float hn = (val - mu) * r * mhg[tid] + mhb[tid];
    float rv = rt[idx];
    float u = (hn + skip[idx]) * (rv / (1.0f + __expf(-rv)));

    __half hi, lo;
    split2h(u, hi, lo);
    size_t b = (size_t)tok * KE_UB + tid;
    ub2[b] = hi; ub2[b + 512] = lo;
}

// ---------------- host launcher ----------------
extern "C" void kernel_launch(void* const* d_in, const int* in_sizes, int n_in,
                              void* d_out, int out_size)
{
    const float* x      = (const float*)d_in[0];
    const float* ln_g   = (const float*)d_in[1];
    const float* ln_b   = (const float*)d_in[2];
    const float* mh_g   = (const float*)d_in[3];
    const float* mh_b   = (const float*)d_in[4];
    const float* W_up_l = (const float*)d_in[5];
    const float* b_up_l = (const float*)d_in[6];
    const float* W_up_r = (const float*)d_in[7];
    const float* b_up_r = (const float*)d_in[8];
    const float* W_down = (const float*)d_in[9];
    const float* b_down = (const float*)d_in[10];
    const float* conv_w = (const float*)d_in[11];
    const float* conv_b = (const float*)d_in[12];
    const float* W_skip = (const float*)d_in[13];
    const float* b_skip = (const float*)d_in[14];
    const float* W_i    = (const float*)d_in[15];
    const float* b_i    = (const float*)d_in[16];
    const float* W_f    = (const float*)d_in[17];
    const float* b_f    = (const float*)d_in[18];
    const float* W_o    = (const float*)d_in[19];
    const float* b_o    = (const float*)d_in[20];
    const float* W_q    = (const float*)d_in[21];
    const float* b_q    = (const float*)d_in[22];
    const float* W_k    = (const float*)d_in[23];
    const float* b_k    = (const float*)d_in[24];
    const float* W_v    = (const float*)d_in[25];
    const float* b_v    = (const float*)d_in[26];
    float* out = (float*)d_out;

    float *rt, *skip, *qb, *kb, *vb, *ob, *ib, *fb, *hsb;
    __half *xn2, *xt2, *xc2, *ub2, *wup, *wqkif, *wskip, *wv, *wo, *wdn;
    cudaGetSymbolAddress((void**)&rt,    g_rt);
    cudaGetSymbolAddress((void**)&skip,  g_skip);
    cudaGetSymbolAddress((void**)&qb,    g_q);
    cudaGetSymbolAddress((void**)&kb,    g_k);
    cudaGetSymbolAddress((void**)&vb,    g_v);
    cudaGetSymbolAddress((void**)&ob,    g_o);
    cudaGetSymbolAddress((void**)&ib,    g_i);
    cudaGetSymbolAddress((void**)&fb,    g_f);
    cudaGetSymbolAddress((void**)&hsb,   g_hs);
    cudaGetSymbolAddress((void**)&xn2,   g_xn2);
    cudaGetSymbolAddress((void**)&xt2,   g_xt2);
    cudaGetSymbolAddress((void**)&xc2,   g_xc2);
    cudaGetSymbolAddress((void**)&ub2,   g_ub2);
    cudaGetSymbolAddress((void**)&wup,   g_wup);
    cudaGetSymbolAddress((void**)&wqkif, g_wqkif);
    cudaGetSymbolAddress((void**)&wskip, g_wskip);
    cudaGetSymbolAddress((void**)&wv,    g_wv);
    cudaGetSymbolAddress((void**)&wo,    g_wo);
    cudaGetSymbolAddress((void**)&wdn,   g_wdn);

    cudaFuncSetAttribute((const void*)gemm_mma<0, KE_XN>, cudaFuncAttributeMaxDynamicSharedMemorySize, GSMEM);
    cudaFuncSetAttribute((const void*)gemm_mma<4, KE_UB>, cudaFuncAttributeMaxDynamicSharedMemorySize, GSMEM);
    cudaFuncSetAttribute((const void*)qkif_v,             cudaFuncAttributeMaxDynamicSharedMemorySize, GSMEM);
    cudaFuncSetAttribute((const void*)skip_o_recur,       cudaFuncAttributeMaxDynamicSharedMemorySize, GSMEM);

    // [0] merged weight conversion + layernorm (wqkif rows 1040..1151 stay zero)
    prep_kernel<<<41088, 256>>>(W_up_l, W_up_r, W_q, W_k, W_i, W_f, W_skip, W_v, W_o, W_down,
                                x, ln_g, ln_b,
                                wup, wqkif, wskip, wv, wo, wdn, xn2);

    // [1] merged up projection: xt2 | rt
    {
        dim3 grid(2560 / NTILE, TOK / MTILE);
        gemm_mma<0, KE_XN><<<grid, 256, GSMEM>>>(xn2, wup, b_up_l, b_up_r,
                                                 nullptr, (float*)xt2, rt);
    }

    // [2] causal conv + silu
    conv_silu_kernel<<<TOK, 256>>>(xt2, conv_w, conv_b, xc2);

    // [3] merged q|k|i|f (xc) + v (xt) — one launch, one tail
    qkif_v<<<832, 256, GSMEM>>>(xc2, xt2, wqkif, wv, b_q, b_k, b_i, b_f, b_v,
                                qb, kb, ib, fb, vb);

    // [4] fused: recurrence (64 blocks first) + skip GEMM + o GEMM
    skip_o_recur<<<576, 256, GSMEM>>>(xc2, xt2, wskip, wo, b_skip, b_o, skip, ob,
                                      qb, kb, vb, ib, fb, hsb);

    // [5] mix -> ub dual
    mix_kernel<<<TOK, 512>>>(hsb, ob, skip, rt, mh_g, mh_b, ub2);

    // [6] down projection + bias + residual
    {
        dim3 grid(1024 / NTILE, TOK / MTILE);
        gemm_mma<4, KE_UB><<<grid, 256, GSMEM>>>(ub2, wdn, b_down, nullptr,
                                                 x, out, nullptr);
    }
}